// round 15
// baseline (speedup 1.0000x reference)
#include <cuda_runtime.h>
#include <cstdint>

// Z gate (DIM=2, S=1) on wires {0,5,11} of a 24-qubit register.
//   out[n] = (-1)^popc(n & SIGN_MASK) * x_real[n]   (N float32)
// SIGN_MASK bits 23,18,12 -> sign uniform over each 2048-float tile
// (tile offsets span bits 0..10 only).
//
// PERSISTENT + SOFTWARE-PIPELINED: 1184 CTAs (148 SMs x 8), each looping
// over 2048-float tiles (one 256-bit chunk per thread per tile). The loop
// prefetches tile i+1's data BEFORE storing tile i, so the load stream never
// drains behind the store stream. Double buffer = 16 data regs; total ~28
// regs keeps 8 CTAs/SM resident (64K regfile budget).

#define SIGN_MASK ((1u << 23) | (1u << 18) | (1u << 12))
#define THREADS   256u
#define TILE_FLOATS 2048u
#define N_TILES   8192u           // (1<<24) / 2048
#define GRID      1184u           // 148 SMs * 8 resident CTAs

struct f8 { float v[8]; };

__device__ __forceinline__ f8 ldg256(const float* p) {
    f8 r;
    asm("ld.global.nc.v8.b32 {%0,%1,%2,%3,%4,%5,%6,%7}, [%8];"
        : "=f"(r.v[0]), "=f"(r.v[1]), "=f"(r.v[2]), "=f"(r.v[3]),
          "=f"(r.v[4]), "=f"(r.v[5]), "=f"(r.v[6]), "=f"(r.v[7])
        : "l"(p));
    return r;
}

__device__ __forceinline__ void stg256_ef(float* p, const f8& r) {
    asm volatile("st.global.L2::evict_first.v8.b32 [%0], {%1,%2,%3,%4,%5,%6,%7,%8};"
                 :: "l"(p),
                    "f"(r.v[0]), "f"(r.v[1]), "f"(r.v[2]), "f"(r.v[3]),
                    "f"(r.v[4]), "f"(r.v[5]), "f"(r.v[6]), "f"(r.v[7])
                 : "memory");
}

__device__ __forceinline__ float tile_sign(unsigned tile) {
    return (__popc((tile << 11) & SIGN_MASK) & 1) ? -1.0f : 1.0f;
}

__global__ void __launch_bounds__(256) z_phase_kernel(
    const float* __restrict__ xr,
    float* __restrict__ out)
{
    unsigned o = threadIdx.x << 3;        // this thread's 32B chunk in a tile

    unsigned tile = blockIdx.x;           // GRID < N_TILES: always valid
    f8 cur = ldg256(xr + (tile << 11) + o);

    for (unsigned next = tile + GRID; next < N_TILES; next += GRID) {
        // Prefetch next tile BEFORE storing the current one.
        f8 nxt = ldg256(xr + (next << 11) + o);

        float s = tile_sign(tile);
        #pragma unroll
        for (int k = 0; k < 8; k++) cur.v[k] *= s;
        stg256_ef(out + (tile << 11) + o, cur);

        tile = next;
        cur = nxt;
    }

    // Drain the last tile.
    float s = tile_sign(tile);
    #pragma unroll
    for (int k = 0; k < 8; k++) cur.v[k] *= s;
    stg256_ef(out + (tile << 11) + o, cur);
}

extern "C" void kernel_launch(void* const* d_in, const int* in_sizes, int n_in,
                              void* d_out, int out_size)
{
    const float* xr = (const float*)d_in[0];
    float* out = (float*)d_out;

    z_phase_kernel<<<GRID, THREADS>>>(xr, out);
}

// round 16
// speedup vs baseline: 1.0363x; 1.0363x over previous
#include <cuda_runtime.h>
#include <cstdint>

// Z gate (DIM=2, S=1) on wires {0,5,11} of a 24-qubit register.
//   out[n] = (-1)^popc(n & SIGN_MASK) * x_real[n]   (N float32)
// SIGN_MASK bits 23,18,12 -> sign uniform over each 4096-float tile.
//
// PERSISTENT (1184 CTAs = 148 SMs x 8) + SOFTWARE PIPELINE, 4096-float tiles:
// each thread owns two 256-bit chunks per tile; the loop prefetches BOTH
// chunks of tile i+1 before storing tile i, so the DRAM read stream never
// drains behind the write stream. ~3.5 iterations per CTA, no wave
// transitions, no ragged tail. Double-buffered data = 32 regs (~44 total).

#define SIGN_MASK ((1u << 23) | (1u << 18) | (1u << 12))
#define THREADS   256u
#define N_TILES   4096u           // (1<<24) / 4096 floats per tile
#define GRID      1184u           // 148 SMs * 8 resident CTAs

struct f8 { float v[8]; };

__device__ __forceinline__ f8 ldg256(const float* p) {
    f8 r;
    asm("ld.global.nc.v8.b32 {%0,%1,%2,%3,%4,%5,%6,%7}, [%8];"
        : "=f"(r.v[0]), "=f"(r.v[1]), "=f"(r.v[2]), "=f"(r.v[3]),
          "=f"(r.v[4]), "=f"(r.v[5]), "=f"(r.v[6]), "=f"(r.v[7])
        : "l"(p));
    return r;
}

__device__ __forceinline__ void stg256_ef(float* p, const f8& r) {
    asm volatile("st.global.L2::evict_first.v8.b32 [%0], {%1,%2,%3,%4,%5,%6,%7,%8};"
                 :: "l"(p),
                    "f"(r.v[0]), "f"(r.v[1]), "f"(r.v[2]), "f"(r.v[3]),
                    "f"(r.v[4]), "f"(r.v[5]), "f"(r.v[6]), "f"(r.v[7])
                 : "memory");
}

__device__ __forceinline__ float tile_sign(unsigned tile) {
    // tile base = tile << 12; only bits >= 12 carry sign.
    return (__popc((tile << 12) & SIGN_MASK) & 1) ? -1.0f : 1.0f;
}

__global__ void __launch_bounds__(256) z_phase_kernel(
    const float* __restrict__ xr,
    float* __restrict__ out)
{
    unsigned o0 = threadIdx.x << 3;                 // chunk in floats 0..2047
    unsigned o1 = (THREADS + threadIdx.x) << 3;     // chunk in floats 2048..4095

    unsigned tile = blockIdx.x;                     // GRID < N_TILES: valid
    f8 a = ldg256(xr + (tile << 12) + o0);
    f8 b = ldg256(xr + (tile << 12) + o1);

    for (unsigned next = tile + GRID; next < N_TILES; next += GRID) {
        // Prefetch next tile's chunks BEFORE storing the current tile.
        f8 na = ldg256(xr + (next << 12) + o0);
        f8 nb = ldg256(xr + (next << 12) + o1);

        float s = tile_sign(tile);
        #pragma unroll
        for (int k = 0; k < 8; k++) { a.v[k] *= s; b.v[k] *= s; }
        stg256_ef(out + (tile << 12) + o0, a);
        stg256_ef(out + (tile << 12) + o1, b);

        tile = next;
        a = na;
        b = nb;
    }

    // Drain the last tile.
    float s = tile_sign(tile);
    #pragma unroll
    for (int k = 0; k < 8; k++) { a.v[k] *= s; b.v[k] *= s; }
    stg256_ef(out + (tile << 12) + o0, a);
    stg256_ef(out + (tile << 12) + o1, b);
}

extern "C" void kernel_launch(void* const* d_in, const int* in_sizes, int n_in,
                              void* d_out, int out_size)
{
    const float* xr = (const float*)d_in[0];
    float* out = (float*)d_out;

    z_phase_kernel<<<GRID, THREADS>>>(xr, out);
}